// round 8
// baseline (speedup 1.0000x reference)
#include <cuda_runtime.h>

#define EPSV 1e-5f
#define RSQRT8 0.35355339059327373f

// scratch (allocation-free rule: device globals)
__device__ float g_q[4*512*64];
__device__ float g_k[4*512*64];
__device__ float g_v[4*512*64];

typedef unsigned long long ull;

__device__ __forceinline__ ull splat2(float x){
    ull r; unsigned u = __float_as_uint(x);
    asm("mov.b64 %0, {%1,%1};" : "=l"(r) : "r"(u));
    return r;
}
__device__ __forceinline__ void fma2a(ull& d, ull a, ull b){
    asm("fma.rn.f32x2 %0, %1, %2, %0;" : "+l"(d) : "l"(a), "l"(b));
}
__device__ __forceinline__ ull mul2(ull a, ull b){
    ull d; asm("mul.rn.f32x2 %0, %1, %2;" : "=l"(d) : "l"(a), "l"(b));
    return d;
}
__device__ __forceinline__ void add2a(ull& d, ull a){
    asm("add.rn.f32x2 %0, %0, %1;" : "+l"(d) : "l"(a));
}
__device__ __forceinline__ float2 unpack2(ull v){
    unsigned lo, hi;
    asm("mov.b64 {%0,%1}, %2;" : "=r"(lo), "=r"(hi) : "l"(v));
    return make_float2(__uint_as_float(lo), __uint_as_float(hi));
}
__device__ __forceinline__ float hsum2(ull v){
    float2 u = unpack2(v); return u.x + u.y;
}
__device__ __forceinline__ void cpa16(const void* sd, const void* g){
    unsigned s = (unsigned)__cvta_generic_to_shared(sd);
    asm volatile("cp.async.cg.shared.global [%0], [%1], 16;" :: "r"(s), "l"(g));
}
__device__ __forceinline__ unsigned tf32r(float x){
    unsigned r; asm("cvt.rna.tf32.f32 %0, %1;" : "=r"(r) : "f"(x)); return r;
}
__device__ __forceinline__ void mma8(float* d, unsigned a0, unsigned a1, unsigned a2, unsigned a3,
                                     unsigned b0, unsigned b1){
    asm("mma.sync.aligned.m16n8k8.row.col.f32.tf32.tf32.f32 "
        "{%0,%1,%2,%3},{%4,%5,%6,%7},{%8,%9},{%0,%1,%2,%3};"
        : "+f"(d[0]), "+f"(d[1]), "+f"(d[2]), "+f"(d[3])
        : "r"(a0), "r"(a1), "r"(a2), "r"(a3), "r"(b0), "r"(b1));
}

// ===================== Kernel 1: LN1 + QKV projection (4 rows/block) =====================
__global__ void __launch_bounds__(256)
qkv_kernel(const float* __restrict__ h, const float* __restrict__ Wh,
           const float* __restrict__ g1, const float* __restrict__ b1)
{
    __shared__ float hn[4][64];
    __shared__ float part[4][4];
    int t = threadIdx.x;
    int g = t >> 6, tl = t & 63;
    int row = blockIdx.x*4 + g;
    float x = h[row*64 + tl];
    float s = x, q = x*x;
    #pragma unroll
    for (int o = 16; o >= 1; o >>= 1){
        s += __shfl_xor_sync(0xffffffffu, s, o);
        q += __shfl_xor_sync(0xffffffffu, q, o);
    }
    if ((tl & 31) == 0){ part[g][tl>>5] = s; part[g][2 + (tl>>5)] = q; }
    __syncthreads();
    float mean = (part[g][0] + part[g][1]) * (1.f/64.f);
    float var  = (part[g][2] + part[g][3]) * (1.f/64.f) - mean*mean;
    float hv = (x - mean) * rsqrtf(var + EPSV) * g1[tl] + b1[tl];
    hn[g][tl] = hv;
    __syncthreads();
    float aq = 0.f, ak = 0.f, av = 0.f;
    #pragma unroll 8
    for (int i = 0; i < 64; i++){
        float z = hn[g][i];
        aq = fmaf(z, Wh[i*192 + tl],       aq);
        ak = fmaf(z, Wh[i*192 + 64 + tl],  ak);
        av = fmaf(z, Wh[i*192 + 128 + tl], av);
    }
    g_q[row*64 + tl] = aq;
    g_k[row*64 + tl] = ak;
    g_v[row*64 + tl] = av;
}

// ===================== Kernel 2: fused edge-GEMM(mma.tf32) + attention + LN2 + MLP =====================
// 256 threads = 8 warps, 4 q-rows/block, k-tile 32, TWO blocks per SM.
// Warp w owns (qrow = w>>1, k-half = w&1) in BOTH phases:
//   Phase1: ew M-rows 16w..16w+15 via mma (A = raw f32-as-tf32, B = rna tf32 in regs).
//   Phase2 (same warp, syncwarp only): lane: hp=lane>>3 -> heads {2hp,2hp+1},
//           g=lane&7 -> tile k-rows {kh*16+2g, +1}. q in registers.
// k_s/v_s use 16B-chunk XOR swizzle: chunk ch of row r at float off r*68 + 4*(ch ^ ((r>>1)&7)).
// ONE __syncthreads per tile (after wait_group; cp.async issued after it -> race-free).
// smem floats: e_s[0,17408) 2x128x68 | k_s[17408,21760) | v_s[21760,26112) | ew_s[26112,28416) 128x18
// overlays: we_raw=ew_s (pre-loop) ; red_s=v_s, y_s=k_s, z_s=ew_s, hid_s=ew_s+256 (post-loop)
__global__ void __launch_bounds__(256, 2)
attn_kernel(const float* __restrict__ e, const float* __restrict__ We,
            const float* __restrict__ hin, const float* __restrict__ w1,
            const float* __restrict__ w2, const float* __restrict__ g2,
            const float* __restrict__ b2, float* __restrict__ out)
{
    extern __shared__ float smem[];
    float* e_s    = smem;
    float* k_s    = smem + 17408;
    float* v_s    = smem + 21760;
    float* ew_s   = smem + 26112;
    float* we_raw = ew_s;
    float* red_s  = v_s;
    float* y_s    = k_s;
    float* z_s    = ew_s;
    float* hid_s  = ew_s + 256;

    const int t    = threadIdx.x;
    const int w    = t >> 5;
    const int lane = t & 31;
    const int hp   = lane >> 3;         // head pair: heads 2hp, 2hp+1
    const int g    = lane & 7;          // k-row pair within half-tile
    const int qrow = w >> 1;
    const int kh   = w & 1;
    const int bx   = blockIdx.x;
    const int b    = bx >> 7;
    const int q0   = (bx & 127) << 2;

    const float* eg = e + ((size_t)(b*512 + q0)) * 512 * 64;
    const float* kg = g_k + (size_t)(b*512) * 64;
    const float* vg = g_v + (size_t)(b*512) * 64;

    // ---- hoisted copy addressing ----
    const int rc = t >> 4;              // 0..15
    const int cc = t & 15;
    const char* peb = (const char*)(eg + (size_t)rc*64 + cc*4);
    const char* pkb = (const char*)(kg + (size_t)rc*64 + cc*4);
    const char* pvb = (const char*)(vg + (size_t)rc*64 + cc*4);
    const int e_dst  = (rc*68 + cc*4) * 4;
    const int kv_dst = (rc*68 + (cc ^ ((rc>>1)&7))*4) * 4;   // swizzled chunk dst (rows rc, rc+16 share xor)

    // ---- group A: W_e ----
    cpa16((char*)we_raw + t*16, We + t*4);
    asm volatile("cp.async.commit_group;");

    // ---- group B: tile 0 ----
    {
        const char* esd = (const char*)e_s + e_dst;
        #pragma unroll
        for (int it = 0; it < 8; it++)
            cpa16(esd + it*4352, peb + (it>>1)*131072 + (it&1)*4096);
        const char* ksd = (const char*)k_s + kv_dst;
        const char* vsd = (const char*)v_s + kv_dst;
        cpa16(ksd, pkb);            cpa16(ksd + 4352, pkb + 4096);
        cpa16(vsd, pvb);            cpa16(vsd + 4352, pvb + 4096);
        asm volatile("cp.async.commit_group;");
    }
    peb += 8192; pkb += 8192; pvb += 8192;

    // ---- q preload into registers: 2 heads x 8 floats ----
    ull qh[2][4];
    {
        const ulonglong2* qp2 = (const ulonglong2*)(g_q + (size_t)(b*512 + q0 + qrow)*64 + hp*16);
        ulonglong2 t0 = qp2[0], t1 = qp2[1], t2 = qp2[2], t3 = qp2[3];
        qh[0][0]=t0.x; qh[0][1]=t0.y; qh[0][2]=t1.x; qh[0][3]=t1.y;
        qh[1][0]=t2.x; qh[1][1]=t2.y; qh[1][2]=t3.x; qh[1][3]=t3.y;
    }

    // ---- wait group A; build persistent B fragments (rna tf32) ----
    asm volatile("cp.async.wait_group 1;");
    __syncthreads();
    unsigned b0f[16], b1f[16];
    {
        const int kq = lane & 3, nq = lane >> 2;
        #pragma unroll
        for (int s = 0; s < 8; s++){
            #pragma unroll
            for (int n = 0; n < 2; n++){
                b0f[s*2+n] = tf32r(we_raw[(s*8 + kq)*16     + n*8 + nq]);
                b1f[s*2+n] = tf32r(we_raw[(s*8 + kq + 4)*16 + n*8 + nq]);
            }
        }
    }

    float l[2] = {0.f, 0.f};            // per head (2hp+hh)
    ull acc[8];                          // [head(2)][d2(4)]
    #pragma unroll
    for (int i = 0; i < 8; i++) acc[i] = 0ull;

    // chunk offsets for phase2 k/v reads (swizzle x = g, constant per lane)
    const int c0 = 4*((4*hp + 0) ^ g);
    const int c1 = 4*((4*hp + 1) ^ g);
    const int c2 = 4*((4*hp + 2) ^ g);
    const int c3 = 4*((4*hp + 3) ^ g);
    const int kt0 = kh*16 + g*2;

    for (int tile = 0; tile < 16; tile++){
        const int buf = tile & 1;
        asm volatile("cp.async.wait_group 0;");
        __syncthreads();   // all warps done with prev tile; this tile's data visible

        if (tile < 15){
            const int nb = buf ^ 1;
            const char* esd = (const char*)(e_s + nb*8704) + e_dst;
            #pragma unroll
            for (int it = 0; it < 8; it++)
                cpa16(esd + it*4352, peb + (it>>1)*131072 + (it&1)*4096);
            const char* ksd = (const char*)(k_s + nb*2176) + kv_dst;
            const char* vsd = (const char*)(v_s + nb*2176) + kv_dst;
            cpa16(ksd, pkb);            cpa16(ksd + 4352, pkb + 4096);
            cpa16(vsd, pvb);            cpa16(vsd + 4352, pvb + 4096);
            asm volatile("cp.async.commit_group;");
            peb += 8192; pkb += 8192; pvb += 8192;
        }

        // ---- Phase 1: ew for own M rows (raw f32 bits as tf32 A operands) ----
        {
            const float* eA = e_s + buf*8704 + (w*16 + (lane>>2))*68 + (lane&3);
            float d0[4] = {0.f,0.f,0.f,0.f};
            float d1[4] = {0.f,0.f,0.f,0.f};
            #pragma unroll
            for (int s = 0; s < 8; s++){
                unsigned a0 = __float_as_uint(eA[s*8]);
                unsigned a2 = __float_as_uint(eA[s*8 + 4]);
                unsigned a1 = __float_as_uint(eA[544 + s*8]);
                unsigned a3 = __float_as_uint(eA[544 + s*8 + 4]);
                mma8(d0, a0, a1, a2, a3, b0f[s*2],   b1f[s*2]);
                mma8(d1, a0, a1, a2, a3, b0f[s*2+1], b1f[s*2+1]);
            }
            float* ewp = ew_s + (w*16 + (lane>>2))*18 + 2*(lane&3);
            *(float2*)(ewp)       = make_float2(d0[0], d0[1]);
            *(float2*)(ewp + 8)   = make_float2(d1[0], d1[1]);
            *(float2*)(ewp + 144) = make_float2(d0[2], d0[3]);
            *(float2*)(ewp + 152) = make_float2(d1[2], d1[3]);
        }
        __syncwarp();      // same-warp produce -> consume

        // ---- Phase 2: 2 heads x 2 k-rows per lane ----
        {
            const float* ewr = ew_s + (w*16 + g*2)*18 + 2*hp;
            float2 e1r0 = *(const float2*)(ewr);
            float2 e2r0 = *(const float2*)(ewr + 8);
            float2 e1r1 = *(const float2*)(ewr + 18);
            float2 e2r1 = *(const float2*)(ewr + 26);

            const float* kb = k_s + buf*2176 + kt0*68;
            const float* vb = v_s + buf*2176 + kt0*68;
            ulonglong2 k00 = *(const ulonglong2*)(kb + c0);
            ulonglong2 k01 = *(const ulonglong2*)(kb + c1);
            ulonglong2 k02 = *(const ulonglong2*)(kb + c2);
            ulonglong2 k03 = *(const ulonglong2*)(kb + c3);
            ulonglong2 k10 = *(const ulonglong2*)(kb + 68 + c0);
            ulonglong2 k11 = *(const ulonglong2*)(kb + 68 + c1);
            ulonglong2 k12 = *(const ulonglong2*)(kb + 68 + c2);
            ulonglong2 k13 = *(const ulonglong2*)(kb + 68 + c3);
            ulonglong2 v00 = *(const ulonglong2*)(vb + c0);
            ulonglong2 v01 = *(const ulonglong2*)(vb + c1);
            ulonglong2 v02 = *(const ulonglong2*)(vb + c2);
            ulonglong2 v03 = *(const ulonglong2*)(vb + c3);
            ulonglong2 v10 = *(const ulonglong2*)(vb + 68 + c0);
            ulonglong2 v11 = *(const ulonglong2*)(vb + 68 + c1);
            ulonglong2 v12 = *(const ulonglong2*)(vb + 68 + c2);
            ulonglong2 v13 = *(const ulonglong2*)(vb + 68 + c3);

            // row0 head0
            { ull s2 = mul2(qh[0][0], k00.x); fma2a(s2, qh[0][1], k00.y);
              fma2a(s2, qh[0][2], k01.x);     fma2a(s2, qh[0][3], k01.y);
              float s = fmaf(hsum2(s2), RSQRT8, e1r0.x);
              float p = __expf(s); l[0] += p;
              ull gg = splat2(p * e2r0.x);
              fma2a(acc[0], gg, v00.x); fma2a(acc[1], gg, v00.y);
              fma2a(acc[2], gg, v01.x); fma2a(acc[3], gg, v01.y); }
            // row0 head1
            { ull s2 = mul2(qh[1][0], k02.x); fma2a(s2, qh[1][1], k02.y);
              fma2a(s2, qh[1][2], k03.x);     fma2a(s2, qh[1][3], k03.y);
              float s = fmaf(hsum2(s2), RSQRT8, e1r0.y);
              float p = __expf(s); l[1] += p;
              ull gg = splat2(p * e2r0.y);
              fma2a(acc[4], gg, v02.x); fma2a(acc[5], gg, v02.y);
              fma2a(acc[6], gg, v03.x); fma2a(acc[7], gg, v03.y); }
            // row1 head0
            { ull s2 = mul2(qh[0][0], k10.x); fma2a(s2, qh[0][1], k10.y);
              fma2a(s2, qh[0][2], k11.x);     fma2a(s2, qh[0][3], k11.y);
              float s = fmaf(hsum2(s2), RSQRT8, e1r1.x);
              float p = __expf(s); l[0] += p;
              ull gg = splat2(p * e2r1.x);
              fma2a(acc[0], gg, v10.x); fma2a(acc[1], gg, v10.y);
              fma2a(acc[2], gg, v11.x); fma2a(acc[3], gg, v11.y); }
            // row1 head1
            { ull s2 = mul2(qh[1][0], k12.x); fma2a(s2, qh[1][1], k12.y);
              fma2a(s2, qh[1][2], k13.x);     fma2a(s2, qh[1][3], k13.y);
              float s = fmaf(hsum2(s2), RSQRT8, e1r1.y);
              float p = __expf(s); l[1] += p;
              ull gg = splat2(p * e2r1.y);
              fma2a(acc[4], gg, v12.x); fma2a(acc[5], gg, v12.y);
              fma2a(acc[6], gg, v13.x); fma2a(acc[7], gg, v13.y); }
        }
    }

    // ---- reduce over the 8 lanes of each head-pair group (offsets 1,2,4 stay in group) ----
    #pragma unroll
    for (int off = 4; off >= 1; off >>= 1){
        l[0] += __shfl_xor_sync(0xffffffffu, l[0], off);
        l[1] += __shfl_xor_sync(0xffffffffu, l[1], off);
        #pragma unroll
        for (int i = 0; i < 8; i++)
            add2a(acc[i], __shfl_xor_sync(0xffffffffu, acc[i], off));
    }

    __syncthreads();   // everyone done reading v_s (red_s overlays it)

    if (g == 0){
        float* base = red_s + kh*320 + qrow*80;
        #pragma unroll
        for (int hh = 0; hh < 2; hh++){
            float* p = base + (2*hp + hh)*10;
            #pragma unroll
            for (int d2 = 0; d2 < 4; d2++){
                float2 u = unpack2(acc[hh*4 + d2]);
                *(float2*)(p + 2*d2) = u;
            }
            p[8] = l[hh];
        }
    }
    __syncthreads();

    // ---- y = (sum over k-halves)/l : one element per thread; y_s overlays k_s ----
    {
        int qr = t >> 6, d = t & 63, hh = d >> 3, j = d & 7;
        int o = qr*80 + hh*10;
        float a  = red_s[o + j] + red_s[320 + o + j];
        float ll = red_s[o + 8] + red_s[320 + o + 8];
        y_s[t] = a * __fdividef(1.f, ll);
    }
    __syncthreads();

    // ---- LN2 over (y + h_in): warps 0..3 -> rows 0..3 ----
    if (w < 4){
        const float* hrow = hin + (size_t)(b*512 + q0 + w) * 64;
        float x0 = y_s[w*64 + lane]      + hrow[lane];
        float x1 = y_s[w*64 + lane + 32] + hrow[lane + 32];
        float s = x0 + x1, sq = x0*x0 + x1*x1;
        #pragma unroll
        for (int o = 16; o >= 1; o >>= 1){
            s  += __shfl_xor_sync(0xffffffffu, s, o);
            sq += __shfl_xor_sync(0xffffffffu, sq, o);
        }
        float mean = s * (1.f/64.f);
        float var  = sq * (1.f/64.f) - mean*mean;
        float rs = rsqrtf(var + EPSV);
        z_s[w*64 + lane]      = (x0 - mean) * rs * g2[lane]      + b2[lane];
        z_s[w*64 + lane + 32] = (x1 - mean) * rs * g2[lane + 32] + b2[lane + 32];
    }
    __syncthreads();

    // ---- hidden = relu(z @ w1)  [4 x 256]: one column per thread ----
    {
        int col = t;
        float a0 = 0.f, a1 = 0.f, a2 = 0.f, a3 = 0.f;
        #pragma unroll 8
        for (int i = 0; i < 64; i++){
            float wvv = w1[i*256 + col];
            a0 = fmaf(z_s[i],       wvv, a0);
            a1 = fmaf(z_s[64 + i],  wvv, a1);
            a2 = fmaf(z_s[128 + i], wvv, a2);
            a3 = fmaf(z_s[192 + i], wvv, a3);
        }
        hid_s[col]       = fmaxf(a0, 0.f);
        hid_s[256 + col] = fmaxf(a1, 0.f);
        hid_s[512 + col] = fmaxf(a2, 0.f);
        hid_s[768 + col] = fmaxf(a3, 0.f);
    }
    __syncthreads();

    // ---- out = hidden @ w2 + y : one output element per thread ----
    {
        int d = t & 63, r = t >> 6;
        float a = 0.f;
        #pragma unroll 8
        for (int j = 0; j < 256; j++)
            a = fmaf(hid_s[r*256 + j], w2[j*64 + d], a);
        out[((size_t)(b*512 + q0 + r)) * 64 + d] = a + y_s[r*64 + d];
    }
}

extern "C" void kernel_launch(void* const* d_in, const int* in_sizes, int n_in,
                              void* d_out, int out_size)
{
    const float* h  = (const float*)d_in[0];
    const float* e  = (const float*)d_in[1];
    const float* Wh = (const float*)d_in[2];
    const float* We = (const float*)d_in[3];
    const float* w1 = (const float*)d_in[4];
    const float* w2 = (const float*)d_in[5];
    const float* g1 = (const float*)d_in[6];
    const float* b1 = (const float*)d_in[7];
    const float* g2 = (const float*)d_in[8];
    const float* b2 = (const float*)d_in[9];
    float* out = (float*)d_out;

    cudaFuncSetAttribute(attn_kernel, cudaFuncAttributeMaxDynamicSharedMemorySize, 113664);

    qkv_kernel<<<512, 256>>>(h, Wh, g1, b1);
    attn_kernel<<<512, 256, 113664>>>(e, We, h, w1, w2, g2, b2, out);
}